// round 2
// baseline (speedup 1.0000x reference)
#include <cuda_runtime.h>

#define ORDER 256
#define HIDDEN 512
#define INPUT_DIM 256
#define BATCH 8192
#define TSTEPS 23
#define SLOPE 0.2f

#define BM 128
#define BN 128
#define BK 8

// Scratch (static device globals; no runtime allocation)
__device__ float g_C[TSTEPS * HIDDEN];                       // C_k = W_m A^k Bv
__device__ float g_U[BATCH * TSTEPS];                        // u[b,t]
__device__ float g_P[(size_t)BATCH * TSTEPS * HIDDEN];       // pre-recurrence term

// ---------------------------------------------------------------------------
// C_k = W_m @ (A^k @ Bv), k = 0..22.  One block, 512 threads.
// ---------------------------------------------------------------------------
__global__ void compute_C(const float* __restrict__ A,
                          const float* __restrict__ Bv,
                          const float* __restrict__ Wm) {
    __shared__ float v[2][ORDER];
    int tid = threadIdx.x;
    if (tid < ORDER) v[0][tid] = Bv[tid];
    __syncthreads();
    int cur = 0;
    for (int k = 0; k < TSTEPS; ++k) {
        float c = 0.f;
        const float* wrow = Wm + (size_t)tid * ORDER;
        #pragma unroll 8
        for (int i = 0; i < ORDER; ++i) c = fmaf(wrow[i], v[cur][i], c);
        g_C[k * HIDDEN + tid] = c;

        float nv = 0.f;
        if (tid < ORDER) {
            const float* arow = A + (size_t)tid * ORDER;
            #pragma unroll 8
            for (int i = 0; i < ORDER; ++i) nv = fmaf(arow[i], v[cur][i], nv);
        }
        __syncthreads();
        if (tid < ORDER) v[1 - cur][tid] = nv;
        cur ^= 1;
        __syncthreads();
    }
}

// ---------------------------------------------------------------------------
// u[b,t] = dot(x[b,t,:], e_x).  One warp per (b,t).
// ---------------------------------------------------------------------------
__global__ void compute_U(const float* __restrict__ X,
                          const float* __restrict__ ex) {
    __shared__ float se[INPUT_DIM];
    int tid = threadIdx.x;
    if (tid < INPUT_DIM) se[tid] = ex[tid];
    __syncthreads();
    int warp = tid >> 5, lane = tid & 31;
    int idx = blockIdx.x * 8 + warp;           // row index (b*23+t)
    const float* xr = X + (size_t)idx * INPUT_DIM;
    float s = 0.f;
    #pragma unroll
    for (int i = 0; i < INPUT_DIM / 32; ++i)
        s = fmaf(xr[lane + 32 * i], se[lane + 32 * i], s);
    #pragma unroll
    for (int o = 16; o; o >>= 1) s += __shfl_xor_sync(0xffffffffu, s, o);
    if (lane == 0) g_U[idx] = s;
}

// ---------------------------------------------------------------------------
// P[r,:] = X[r,:] @ W_x  +  sum_{s<=t} U[b,s] * C[t-s][:],  r = b*23+t
// M=188416, K=256, N=512.  128x128x8 tile, 256 threads, 8x8 microtile.
// ---------------------------------------------------------------------------
__global__ void __launch_bounds__(256) gemm_p(const float* __restrict__ X,
                                              const float* __restrict__ Wx) {
    __shared__ float As[BK][BM];
    __shared__ float Bs[BK][BN];
    __shared__ float Cs[TSTEPS][BN];   // staged slice of g_C for this col block

    int tid = threadIdx.x;
    int rowBase = blockIdx.x * BM;
    int colBase = blockIdx.y * BN;

    int aRow = tid >> 1;
    int aCol = (tid & 1) * 4;
    int bK   = tid >> 5;
    int bCol = (tid & 31) * 4;

    int ty = tid >> 4, tx = tid & 15;
    int mBase = ty * 8, nBase = tx * 8;

    float acc[8][8];
    #pragma unroll
    for (int i = 0; i < 8; i++)
        #pragma unroll
        for (int j = 0; j < 8; j++) acc[i][j] = 0.f;

    // Stage C slice (overlaps with first tile loads; no dependency until epilogue)
    for (int idx = tid; idx < TSTEPS * BN; idx += 256) {
        int k = idx >> 7, n = idx & 127;
        Cs[k][n] = g_C[k * HIDDEN + colBase + n];
    }

    for (int k0 = 0; k0 < INPUT_DIM; k0 += BK) {
        float4 av = *(const float4*)(X + (size_t)(rowBase + aRow) * INPUT_DIM + k0 + aCol);
        As[aCol + 0][aRow] = av.x;
        As[aCol + 1][aRow] = av.y;
        As[aCol + 2][aRow] = av.z;
        As[aCol + 3][aRow] = av.w;
        float4 bv = *(const float4*)(Wx + (size_t)(k0 + bK) * HIDDEN + colBase + bCol);
        *(float4*)&Bs[bK][bCol] = bv;
        __syncthreads();
        #pragma unroll
        for (int kk = 0; kk < BK; ++kk) {
            float ra[8], rb[8];
            #pragma unroll
            for (int i = 0; i < 8; i++) ra[i] = As[kk][mBase + i];
            #pragma unroll
            for (int j = 0; j < 8; j++) rb[j] = Bs[kk][nBase + j];
            #pragma unroll
            for (int i = 0; i < 8; i++)
                #pragma unroll
                for (int j = 0; j < 8; j++)
                    acc[i][j] = fmaf(ra[i], rb[j], acc[i][j]);
        }
        __syncthreads();
    }

    // Epilogue: triangular U*C term, then store P
    #pragma unroll
    for (int i = 0; i < 8; i++) {
        int r = rowBase + mBase + i;
        int b = r / TSTEPS;
        int t = r - b * TSTEPS;
        const float* Ub = g_U + b * TSTEPS;
        for (int s = 0; s <= t; ++s) {
            float u = Ub[s];
            const float* cv = &Cs[t - s][nBase];
            #pragma unroll
            for (int j = 0; j < 8; j++) acc[i][j] = fmaf(u, cv[j], acc[i][j]);
        }
        float* prow = g_P + (size_t)r * HIDDEN + colBase + nBase;
        *(float4*)(prow + 0) = make_float4(acc[i][0], acc[i][1], acc[i][2], acc[i][3]);
        *(float4*)(prow + 4) = make_float4(acc[i][4], acc[i][5], acc[i][6], acc[i][7]);
    }
}

// ---------------------------------------------------------------------------
// H_0 = leaky_relu(P_0), written into out[b][0][:]
// ---------------------------------------------------------------------------
__global__ void relu0(float* __restrict__ out) {
    int idx = blockIdx.x * blockDim.x + threadIdx.x;   // over BATCH*HIDDEN
    int b = idx >> 9;
    int j = idx & (HIDDEN - 1);
    size_t off = (size_t)b * TSTEPS * HIDDEN + j;      // t = 0
    float v = g_P[off];
    out[off] = v >= 0.f ? v : SLOPE * v;
}

// ---------------------------------------------------------------------------
// H_t = leaky_relu(P_t + H_{t-1} @ W_h^T).  M=8192, N=512, K=512.
// Reads H_{t-1} and writes H_t directly in out (layout [B][T][H]).
// ---------------------------------------------------------------------------
__global__ void __launch_bounds__(256) gemm_h(const float* __restrict__ Wh,
                                              float* __restrict__ out, int t) {
    __shared__ float As[BK][BM];
    __shared__ float Bs[BK][BN];

    int tid = threadIdx.x;
    int rowBase = blockIdx.x * BM;   // batch
    int colBase = blockIdx.y * BN;   // hidden out

    const size_t rstride = (size_t)TSTEPS * HIDDEN;
    const float* Hprev = out + (size_t)(t - 1) * HIDDEN;

    int aRow = tid >> 1;
    int aCol = (tid & 1) * 4;
    int bN   = tid >> 1;             // W_h row (= output col), transposed load
    int bK4  = (tid & 1) * 4;

    int ty = tid >> 4, tx = tid & 15;
    int mBase = ty * 8, nBase = tx * 8;

    float acc[8][8];
    #pragma unroll
    for (int i = 0; i < 8; i++)
        #pragma unroll
        for (int j = 0; j < 8; j++) acc[i][j] = 0.f;

    for (int k0 = 0; k0 < HIDDEN; k0 += BK) {
        float4 av = *(const float4*)(Hprev + (size_t)(rowBase + aRow) * rstride + k0 + aCol);
        As[aCol + 0][aRow] = av.x;
        As[aCol + 1][aRow] = av.y;
        As[aCol + 2][aRow] = av.z;
        As[aCol + 3][aRow] = av.w;
        float4 bv = *(const float4*)(Wh + (size_t)(colBase + bN) * HIDDEN + k0 + bK4);
        Bs[bK4 + 0][bN] = bv.x;
        Bs[bK4 + 1][bN] = bv.y;
        Bs[bK4 + 2][bN] = bv.z;
        Bs[bK4 + 3][bN] = bv.w;
        __syncthreads();
        #pragma unroll
        for (int kk = 0; kk < BK; ++kk) {
            float ra[8], rb[8];
            #pragma unroll
            for (int i = 0; i < 8; i++) ra[i] = As[kk][mBase + i];
            #pragma unroll
            for (int j = 0; j < 8; j++) rb[j] = Bs[kk][nBase + j];
            #pragma unroll
            for (int i = 0; i < 8; i++)
                #pragma unroll
                for (int j = 0; j < 8; j++)
                    acc[i][j] = fmaf(ra[i], rb[j], acc[i][j]);
        }
        __syncthreads();
    }

    #pragma unroll
    for (int i = 0; i < 8; i++) {
        int b = rowBase + mBase + i;
        size_t off = (size_t)b * rstride + (size_t)t * HIDDEN + colBase + nBase;
        const float* prow = g_P + off;
        float* orow = out + off;
        float4 p0 = *(const float4*)(prow + 0);
        float4 p1 = *(const float4*)(prow + 4);
        float v0 = acc[i][0] + p0.x, v1 = acc[i][1] + p0.y;
        float v2 = acc[i][2] + p0.z, v3 = acc[i][3] + p0.w;
        float v4 = acc[i][4] + p1.x, v5 = acc[i][5] + p1.y;
        float v6 = acc[i][6] + p1.z, v7 = acc[i][7] + p1.w;
        v0 = v0 >= 0.f ? v0 : SLOPE * v0;
        v1 = v1 >= 0.f ? v1 : SLOPE * v1;
        v2 = v2 >= 0.f ? v2 : SLOPE * v2;
        v3 = v3 >= 0.f ? v3 : SLOPE * v3;
        v4 = v4 >= 0.f ? v4 : SLOPE * v4;
        v5 = v5 >= 0.f ? v5 : SLOPE * v5;
        v6 = v6 >= 0.f ? v6 : SLOPE * v6;
        v7 = v7 >= 0.f ? v7 : SLOPE * v7;
        *(float4*)(orow + 0) = make_float4(v0, v1, v2, v3);
        *(float4*)(orow + 4) = make_float4(v4, v5, v6, v7);
    }
}

// ---------------------------------------------------------------------------
extern "C" void kernel_launch(void* const* d_in, const int* in_sizes, int n_in,
                              void* d_out, int out_size) {
    const float* X  = (const float*)d_in[0];  // (8192,23,256)
    const float* A  = (const float*)d_in[1];  // (256,256)
    const float* Bv = (const float*)d_in[2];  // (256,1)
    const float* Wh = (const float*)d_in[3];  // (512,512)
    const float* Wm = (const float*)d_in[4];  // (512,256)
    const float* Wx = (const float*)d_in[5];  // (256,512)
    const float* ex = (const float*)d_in[6];  // (256,1)
    float* out = (float*)d_out;               // (8192,23,512)

    compute_C<<<1, 512>>>(A, Bv, Wm);
    compute_U<<<(BATCH * TSTEPS) / 8, 256>>>(X, ex);

    dim3 gp((BATCH * TSTEPS) / BM, HIDDEN / BN);
    gemm_p<<<gp, 256>>>(X, Wx);

    relu0<<<(BATCH * HIDDEN) / 256, 256>>>(out);

    dim3 gh(BATCH / BM, HIDDEN / BN);
    for (int t = 1; t < TSTEPS; ++t)
        gemm_h<<<gh, 256>>>(Wh, out, t);
}

// round 3
// speedup vs baseline: 1.1803x; 1.1803x over previous
#include <cuda_runtime.h>
#include <cuda_bf16.h>
#include <cstdint>

#define ORDER 256
#define HIDDEN 512
#define INPUT_DIM 256
#define BATCH 8192
#define TSTEPS 23
#define SLOPE 0.2f

#define BM 128
#define BN 128
#define BKH 32          // k-block for tensor GEMMs
#define KP (BKH/2)      // 16 kpairs per block
#define SST 17          // padded smem row stride in u32 words

// ---------------- scratch (static device globals) ----------------
__device__ float g_C[TSTEPS * HIDDEN];                    // C_k = W_m A^k Bv
__device__ float g_U[BATCH * TSTEPS];                     // u[b,t]
__device__ float g_P[(size_t)BATCH * TSTEPS * HIDDEN];    // pre-recurrence term
// pre-split weights: packed bf16 k-pairs (lo half = even k)
__device__ unsigned g_WhHu[512 * 256];  // [n][kpair]  hi
__device__ unsigned g_WhLu[512 * 256];  //             lo
__device__ unsigned g_WxHu[512 * 128];  // [n][kpair] of Wx^T  hi
__device__ unsigned g_WxLu[512 * 128];  //                     lo

// ---------------- helpers ----------------
__device__ __forceinline__ uint2 split_pair(float x0, float x1) {
    __nv_bfloat162 h = __floats2bfloat162_rn(x0, x1);
    float r0 = x0 - __bfloat162float(__low2bfloat16(h));
    float r1 = x1 - __bfloat162float(__high2bfloat16(h));
    __nv_bfloat162 l = __floats2bfloat162_rn(r0, r1);
    return make_uint2(*reinterpret_cast<unsigned*>(&h),
                      *reinterpret_cast<unsigned*>(&l));
}

__device__ __forceinline__ void mma16816(float* d, const unsigned* a, const unsigned* b) {
    asm volatile(
        "mma.sync.aligned.m16n8k16.row.col.f32.bf16.bf16.f32 "
        "{%0,%1,%2,%3},{%4,%5,%6,%7},{%8,%9},{%0,%1,%2,%3};\n"
        : "+f"(d[0]), "+f"(d[1]), "+f"(d[2]), "+f"(d[3])
        : "r"(a[0]), "r"(a[1]), "r"(a[2]), "r"(a[3]), "r"(b[0]), "r"(b[1]));
}

// ---------------------------------------------------------------------------
// Pre-split weights. Wh: [n][k] natural (B[k][n] = Wh[n][k]).
// ---------------------------------------------------------------------------
__global__ void convert_Wh(const float* __restrict__ Wh) {
    int idx = blockIdx.x * blockDim.x + threadIdx.x;   // 512*256
    int n = idx >> 8, p = idx & 255;
    uint2 s = split_pair(Wh[n * 512 + 2 * p], Wh[n * 512 + 2 * p + 1]);
    g_WhHu[idx] = s.x;
    g_WhLu[idx] = s.y;
}
// Wx^T: stored [n][kpair], value = Wx[k][n]
__global__ void convert_Wx(const float* __restrict__ Wx) {
    int idx = blockIdx.x * blockDim.x + threadIdx.x;   // 512*128
    int n = idx >> 7, p = idx & 127;
    uint2 s = split_pair(Wx[(2 * p) * 512 + n], Wx[(2 * p + 1) * 512 + n]);
    g_WxHu[idx] = s.x;
    g_WxLu[idx] = s.y;
}

// ---------------------------------------------------------------------------
// C_k = W_m @ (A^k @ Bv), k = 0..22.  One block, 512 threads.
// ---------------------------------------------------------------------------
__global__ void compute_C(const float* __restrict__ A,
                          const float* __restrict__ Bv,
                          const float* __restrict__ Wm) {
    __shared__ float v[2][ORDER];
    int tid = threadIdx.x;
    if (tid < ORDER) v[0][tid] = Bv[tid];
    __syncthreads();
    int cur = 0;
    for (int k = 0; k < TSTEPS; ++k) {
        float c = 0.f;
        const float* wrow = Wm + (size_t)tid * ORDER;
        #pragma unroll 8
        for (int i = 0; i < ORDER; ++i) c = fmaf(wrow[i], v[cur][i], c);
        g_C[k * HIDDEN + tid] = c;
        float nv = 0.f;
        if (tid < ORDER) {
            const float* arow = A + (size_t)tid * ORDER;
            #pragma unroll 8
            for (int i = 0; i < ORDER; ++i) nv = fmaf(arow[i], v[cur][i], nv);
        }
        __syncthreads();
        if (tid < ORDER) v[1 - cur][tid] = nv;
        cur ^= 1;
        __syncthreads();
    }
}

// ---------------------------------------------------------------------------
// u[b,t] = dot(x[b,t,:], e_x).  One warp per (b,t).
// ---------------------------------------------------------------------------
__global__ void compute_U(const float* __restrict__ X,
                          const float* __restrict__ ex) {
    __shared__ float se[INPUT_DIM];
    int tid = threadIdx.x;
    if (tid < INPUT_DIM) se[tid] = ex[tid];
    __syncthreads();
    int warp = tid >> 5, lane = tid & 31;
    int idx = blockIdx.x * 8 + warp;
    const float* xr = X + (size_t)idx * INPUT_DIM;
    float s = 0.f;
    #pragma unroll
    for (int i = 0; i < INPUT_DIM / 32; ++i)
        s = fmaf(xr[lane + 32 * i], se[lane + 32 * i], s);
    #pragma unroll
    for (int o = 16; o; o >>= 1) s += __shfl_xor_sync(0xffffffffu, s, o);
    if (lane == 0) g_U[idx] = s;
}

// ---------------------------------------------------------------------------
// Tensor-core P GEMM: P = X @ Wx + triangular(U, C).  M=188416, K=256, N=512.
// CTA 128x128, 512 thr (16 warps, 4x4 grid of 32x32 warp tiles), BK=32.
// ---------------------------------------------------------------------------
__global__ void __launch_bounds__(512) gemm_p_tc(const float* __restrict__ X) {
    __shared__ unsigned AsH[BM][SST], AsL[BM][SST];
    __shared__ unsigned BsH[BN][SST], BsL[BN][SST];
    __shared__ float Cs[TSTEPS][BN];

    int tid = threadIdx.x;
    int warp = tid >> 5, lane = tid & 31;
    int g = lane >> 2, tig = lane & 3;
    int wm = warp >> 2, wn = warp & 3;
    int rowBase = blockIdx.x * BM;
    int colBase = blockIdx.y * BN;

    // stage C slice for epilogue
    for (int i = tid; i < TSTEPS * BN; i += 512) {
        int k = i >> 7, n = i & 127;
        Cs[k][n] = g_C[k * HIDDEN + colBase + n];
    }

    float acc[2][4][4];
    #pragma unroll
    for (int a = 0; a < 2; a++)
        #pragma unroll
        for (int b = 0; b < 4; b++)
            #pragma unroll
            for (int c = 0; c < 4; c++) acc[a][b][c] = 0.f;

    for (int k0 = 0; k0 < INPUT_DIM; k0 += BKH) {
        // A: 128 rows x 32 cols fp32, split on the fly
        #pragma unroll
        for (int i = 0; i < 2; i++) {
            int q = tid + i * 512;
            int row = q >> 3, f4 = q & 7;
            const float4 v = *(const float4*)(X + (size_t)(rowBase + row) * INPUT_DIM + k0 + f4 * 4);
            uint2 p0 = split_pair(v.x, v.y);
            uint2 p1 = split_pair(v.z, v.w);
            AsH[row][f4 * 2] = p0.x;     AsL[row][f4 * 2] = p0.y;
            AsH[row][f4 * 2 + 1] = p1.x; AsL[row][f4 * 2 + 1] = p1.y;
        }
        // B: pre-split Wx^T, 128 rows(n) x 16 kpairs
        {
            int row = tid >> 2, u4 = tid & 3;
            size_t base = (size_t)(colBase + row) * 128 + (k0 >> 1) + u4 * 4;
            uint4 h = *(const uint4*)(g_WxHu + base);
            uint4 l = *(const uint4*)(g_WxLu + base);
            BsH[row][u4 * 4 + 0] = h.x; BsH[row][u4 * 4 + 1] = h.y;
            BsH[row][u4 * 4 + 2] = h.z; BsH[row][u4 * 4 + 3] = h.w;
            BsL[row][u4 * 4 + 0] = l.x; BsL[row][u4 * 4 + 1] = l.y;
            BsL[row][u4 * 4 + 2] = l.z; BsL[row][u4 * 4 + 3] = l.w;
        }
        __syncthreads();

        int m0 = wm * 32, n0 = wn * 32;
        #pragma unroll
        for (int kk = 0; kk < 2; kk++) {
            int kb = kk * 8;
            unsigned aH[2][4], aL[2][4];
            #pragma unroll
            for (int mt = 0; mt < 2; mt++) {
                int r0 = m0 + mt * 16 + g;
                aH[mt][0] = AsH[r0][kb + tig];     aH[mt][1] = AsH[r0 + 8][kb + tig];
                aH[mt][2] = AsH[r0][kb + tig + 4]; aH[mt][3] = AsH[r0 + 8][kb + tig + 4];
                aL[mt][0] = AsL[r0][kb + tig];     aL[mt][1] = AsL[r0 + 8][kb + tig];
                aL[mt][2] = AsL[r0][kb + tig + 4]; aL[mt][3] = AsL[r0 + 8][kb + tig + 4];
            }
            unsigned bH[4][2], bL[4][2];
            #pragma unroll
            for (int nt = 0; nt < 4; nt++) {
                int c = n0 + nt * 8 + g;
                bH[nt][0] = BsH[c][kb + tig]; bH[nt][1] = BsH[c][kb + tig + 4];
                bL[nt][0] = BsL[c][kb + tig]; bL[nt][1] = BsL[c][kb + tig + 4];
            }
            #pragma unroll
            for (int mt = 0; mt < 2; mt++)
                #pragma unroll
                for (int nt = 0; nt < 4; nt++) {
                    mma16816(acc[mt][nt], aH[mt], bH[nt]);
                    mma16816(acc[mt][nt], aH[mt], bL[nt]);
                    mma16816(acc[mt][nt], aL[mt], bH[nt]);
                }
        }
        __syncthreads();
    }

    // epilogue: triangular U*C + store P
    int m0 = wm * 32, n0 = wn * 32;
    #pragma unroll
    for (int mt = 0; mt < 2; mt++) {
        #pragma unroll
        for (int half = 0; half < 2; half++) {
            int r = rowBase + m0 + mt * 16 + g + half * 8;
            int b = r / TSTEPS;
            int t = r - b * TSTEPS;
            const float* Ub = g_U + b * TSTEPS;
            #pragma unroll
            for (int nt = 0; nt < 4; nt++) {
                int col = n0 + nt * 8 + tig * 2;
                float v0 = acc[mt][nt][half * 2];
                float v1 = acc[mt][nt][half * 2 + 1];
                for (int s = 0; s <= t; ++s) {
                    float u = Ub[s];
                    v0 = fmaf(u, Cs[t - s][col], v0);
                    v1 = fmaf(u, Cs[t - s][col + 1], v1);
                }
                float* prow = g_P + (size_t)r * HIDDEN + colBase + col;
                *(float2*)prow = make_float2(v0, v1);
            }
        }
    }
}

// ---------------------------------------------------------------------------
// H_0 = leaky_relu(P_0)
// ---------------------------------------------------------------------------
__global__ void relu0(float* __restrict__ out) {
    int idx = blockIdx.x * blockDim.x + threadIdx.x;
    int b = idx >> 9;
    int j = idx & (HIDDEN - 1);
    size_t off = (size_t)b * TSTEPS * HIDDEN + j;
    float v = g_P[off];
    out[off] = v >= 0.f ? v : SLOPE * v;
}

// ---------------------------------------------------------------------------
// Tensor-core recurrence step: H_t = lrelu(P_t + H_{t-1} @ Wh^T).
// M=8192, N=512, K=512.  Same tiling as gemm_p_tc.
// ---------------------------------------------------------------------------
__global__ void __launch_bounds__(512) gemm_h_tc(float* __restrict__ out, int t) {
    __shared__ unsigned AsH[BM][SST], AsL[BM][SST];
    __shared__ unsigned BsH[BN][SST], BsL[BN][SST];

    int tid = threadIdx.x;
    int warp = tid >> 5, lane = tid & 31;
    int g = lane >> 2, tig = lane & 3;
    int wm = warp >> 2, wn = warp & 3;
    int rowBase = blockIdx.x * BM;
    int colBase = blockIdx.y * BN;

    const size_t rstride = (size_t)TSTEPS * HIDDEN;
    const float* Hprev = out + (size_t)(t - 1) * HIDDEN;

    float acc[2][4][4];
    #pragma unroll
    for (int a = 0; a < 2; a++)
        #pragma unroll
        for (int b = 0; b < 4; b++)
            #pragma unroll
            for (int c = 0; c < 4; c++) acc[a][b][c] = 0.f;

    for (int k0 = 0; k0 < HIDDEN; k0 += BKH) {
        #pragma unroll
        for (int i = 0; i < 2; i++) {
            int q = tid + i * 512;
            int row = q >> 3, f4 = q & 7;
            const float4 v = *(const float4*)(Hprev + (size_t)(rowBase + row) * rstride + k0 + f4 * 4);
            uint2 p0 = split_pair(v.x, v.y);
            uint2 p1 = split_pair(v.z, v.w);
            AsH[row][f4 * 2] = p0.x;     AsL[row][f4 * 2] = p0.y;
            AsH[row][f4 * 2 + 1] = p1.x; AsL[row][f4 * 2 + 1] = p1.y;
        }
        {
            int row = tid >> 2, u4 = tid & 3;
            size_t base = (size_t)(colBase + row) * 256 + (k0 >> 1) + u4 * 4;
            uint4 h = *(const uint4*)(g_WhHu + base);
            uint4 l = *(const uint4*)(g_WhLu + base);
            BsH[row][u4 * 4 + 0] = h.x; BsH[row][u4 * 4 + 1] = h.y;
            BsH[row][u4 * 4 + 2] = h.z; BsH[row][u4 * 4 + 3] = h.w;
            BsL[row][u4 * 4 + 0] = l.x; BsL[row][u4 * 4 + 1] = l.y;
            BsL[row][u4 * 4 + 2] = l.z; BsL[row][u4 * 4 + 3] = l.w;
        }
        __syncthreads();

        int m0 = wm * 32, n0 = wn * 32;
        #pragma unroll
        for (int kk = 0; kk < 2; kk++) {
            int kb = kk * 8;
            unsigned aH[2][4], aL[2][4];
            #pragma unroll
            for (int mt = 0; mt < 2; mt++) {
                int r0 = m0 + mt * 16 + g;
                aH[mt][0] = AsH[r0][kb + tig];     aH[mt][1] = AsH[r0 + 8][kb + tig];
                aH[mt][2] = AsH[r0][kb + tig + 4]; aH[mt][3] = AsH[r0 + 8][kb + tig + 4];
                aL[mt][0] = AsL[r0][kb + tig];     aL[mt][1] = AsL[r0 + 8][kb + tig];
                aL[mt][2] = AsL[r0][kb + tig + 4]; aL[mt][3] = AsL[r0 + 8][kb + tig + 4];
            }
            unsigned bH[4][2], bL[4][2];
            #pragma unroll
            for (int nt = 0; nt < 4; nt++) {
                int c = n0 + nt * 8 + g;
                bH[nt][0] = BsH[c][kb + tig]; bH[nt][1] = BsH[c][kb + tig + 4];
                bL[nt][0] = BsL[c][kb + tig]; bL[nt][1] = BsL[c][kb + tig + 4];
            }
            #pragma unroll
            for (int mt = 0; mt < 2; mt++)
                #pragma unroll
                for (int nt = 0; nt < 4; nt++) {
                    mma16816(acc[mt][nt], aH[mt], bH[nt]);
                    mma16816(acc[mt][nt], aH[mt], bL[nt]);
                    mma16816(acc[mt][nt], aL[mt], bH[nt]);
                }
        }
        __syncthreads();
    }

    // epilogue: add P, leaky relu, store H_t
    int m0 = wm * 32, n0 = wn * 32;
    #pragma unroll
    for (int mt = 0; mt < 2; mt++) {
        #pragma unroll
        for (int half = 0; half < 2; half++) {
            int b = rowBase + m0 + mt * 16 + g + half * 8;
            #pragma unroll
            for (int nt = 0; nt < 4; nt++) {
                int col = colBase + n0 + nt * 8 + tig * 2;
                size_t off = (size_t)b * rstride + (size_t)t * HIDDEN + col;
                float2 p = *(const float2*)(g_P + off);
                float v0 = acc[mt][nt][half * 2] + p.x;
                float v1 = acc[mt][nt][half * 2 + 1] + p.y;
                v0 = v0 >= 0.f ? v0 : SLOPE * v0;
                v1 = v1 >= 0.f ? v1 : SLOPE * v1;
                *(float2*)(out + off) = make_float2(v0, v1);
            }
        }
    }
}

// ---------------------------------------------------------------------------
extern "C" void kernel_launch(void* const* d_in, const int* in_sizes, int n_in,
                              void* d_out, int out_size) {
    const float* X  = (const float*)d_in[0];  // (8192,23,256)
    const float* A  = (const float*)d_in[1];  // (256,256)
    const float* Bv = (const float*)d_in[2];  // (256,1)
    const float* Wh = (const float*)d_in[3];  // (512,512)
    const float* Wm = (const float*)d_in[4];  // (512,256)
    const float* Wx = (const float*)d_in[5];  // (256,512)
    const float* ex = (const float*)d_in[6];  // (256,1)
    float* out = (float*)d_out;               // (8192,23,512)

    convert_Wh<<<512, 256>>>(Wh);
    convert_Wx<<<256, 256>>>(Wx);
    compute_C<<<1, 512>>>(A, Bv, Wm);
    compute_U<<<(BATCH * TSTEPS) / 8, 256>>>(X, ex);

    dim3 gp((BATCH * TSTEPS) / BM, HIDDEN / BN);
    gemm_p_tc<<<gp, 512>>>(X);

    relu0<<<(BATCH * HIDDEN) / 256, 256>>>(out);

    dim3 gh(BATCH / BM, HIDDEN / BN);
    for (int t = 1; t < TSTEPS; ++t)
        gemm_h_tc<<<gh, 512>>>(out, t);
}

// round 6
// speedup vs baseline: 1.5376x; 1.3027x over previous
#include <cuda_runtime.h>
#include <cuda_bf16.h>
#include <cstdint>

typedef unsigned short u16;
typedef unsigned int u32;

#define ORDER 256
#define HIDDEN 512
#define INPUT_DIM 256
#define BATCH 8192
#define TSTEPS 23
#define SLOPE 0.2f

#define KCH 32                   // K per pipeline chunk
#define TILE_ROW_B 64            // 32 bf16 per row
#define OPER_B (128 * TILE_ROW_B)   // 8 KB per operand tile
#define STAGE_B (4 * OPER_B)        // AH, AL, BH, BL = 32 KB
#define SMEM_H (2 * STAGE_B)                            // 64 KB
#define SMEM_P (2 * STAGE_B + TSTEPS * 128 * 4 + 184 * 4)  // +Cs +U

// ---------------- scratch ----------------
__device__ float g_C[TSTEPS * HIDDEN];
__device__ float g_U[BATCH * TSTEPS];
__device__ float g_P[(size_t)BATCH * TSTEPS * HIDDEN];
__device__ __align__(16) u16 g_WhH[512 * 512];   // [n][k]
__device__ __align__(16) u16 g_WhL[512 * 512];
__device__ __align__(16) u16 g_WxH[512 * 256];   // [n][k] = Wx[k][n]
__device__ __align__(16) u16 g_WxL[512 * 256];
__device__ __align__(16) u16 g_XH[(size_t)BATCH * TSTEPS * 256];
__device__ __align__(16) u16 g_XL[(size_t)BATCH * TSTEPS * 256];
__device__ __align__(16) u16 g_HH0[BATCH * 512], g_HL0[BATCH * 512];
__device__ __align__(16) u16 g_HH1[BATCH * 512], g_HL1[BATCH * 512];

// ---------------- low-level helpers ----------------
__device__ __forceinline__ u32 smem_u32(const void* p) {
    u32 a;
    asm("{ .reg .u64 t; cvta.to.shared.u64 t, %1; cvt.u32.u64 %0, t; }" : "=r"(a) : "l"(p));
    return a;
}
__device__ __forceinline__ u32 swz(u32 off) { return off ^ ((off >> 3) & 0x30); }

__device__ __forceinline__ void cp16(u32 dst, const void* src) {
    asm volatile("cp.async.cg.shared.global [%0], [%1], 16;" :: "r"(dst), "l"(src));
}
__device__ __forceinline__ void cp_commit() { asm volatile("cp.async.commit_group;" ::: "memory"); }
__device__ __forceinline__ void cp_wait1() { asm volatile("cp.async.wait_group 1;" ::: "memory"); }
__device__ __forceinline__ void cp_wait0() { asm volatile("cp.async.wait_group 0;" ::: "memory"); }

__device__ __forceinline__ void ldsm4(u32* r, u32 a) {
    asm volatile("ldmatrix.sync.aligned.m8n8.x4.shared.b16 {%0,%1,%2,%3}, [%4];"
                 : "=r"(r[0]), "=r"(r[1]), "=r"(r[2]), "=r"(r[3]) : "r"(a));
}
__device__ __forceinline__ void mma(float* d, const u32* a, u32 b0, u32 b1) {
    asm volatile(
        "mma.sync.aligned.m16n8k16.row.col.f32.bf16.bf16.f32 "
        "{%0,%1,%2,%3},{%4,%5,%6,%7},{%8,%9},{%0,%1,%2,%3};\n"
        : "+f"(d[0]), "+f"(d[1]), "+f"(d[2]), "+f"(d[3])
        : "r"(a[0]), "r"(a[1]), "r"(a[2]), "r"(a[3]), "r"(b0), "r"(b1));
}
__device__ __forceinline__ void split2(float x0, float x1, u32& hi, u32& lo) {
    __nv_bfloat162 h = __floats2bfloat162_rn(x0, x1);
    float r0 = x0 - __bfloat162float(__low2bfloat16(h));
    float r1 = x1 - __bfloat162float(__high2bfloat16(h));
    __nv_bfloat162 l = __floats2bfloat162_rn(r0, r1);
    hi = *reinterpret_cast<u32*>(&h);
    lo = *reinterpret_cast<u32*>(&l);
}

// ---------------- stage loader: 8 cp16 per thread ----------------
__device__ __forceinline__ void stage_load(u32 sbase, int kdim,
                                           const u16* __restrict__ AH, const u16* __restrict__ AL,
                                           size_t aRowBase,
                                           const u16* __restrict__ BH, const u16* __restrict__ BL,
                                           int colBase, int k0, int tid) {
    #pragma unroll
    for (int j = 0; j < 2; j++) {
        int idx = j * 256 + tid;
        int row = idx >> 2, c = idx & 3;
        u32 d = sbase + swz((u32)(row * 64 + c * 16));
        size_t gi = (aRowBase + row) * kdim + k0 + c * 8;
        cp16(d, AH + gi);
        cp16(d + OPER_B, AL + gi);
    }
    #pragma unroll
    for (int j = 0; j < 2; j++) {
        int idx = j * 256 + tid;
        int row = idx >> 2, c = idx & 3;
        u32 d = sbase + 2 * OPER_B + swz((u32)(row * 64 + c * 16));
        size_t gi = (size_t)(colBase + row) * kdim + k0 + c * 8;
        cp16(d, BH + gi);
        cp16(d + OPER_B, BL + gi);
    }
}

// ---------------- stage compute: 96 HMMA per warp ----------------
__device__ __forceinline__ void stage_compute(u32 sbase, float acc[2][8][4],
                                              int wm, int wn, int lane) {
    u32 aH = sbase, aL = sbase + OPER_B, bH = sbase + 2 * OPER_B, bL = sbase + 3 * OPER_B;
    int rA = (lane & 7) + ((lane >> 3) & 1) * 8;
    int cA = lane >> 4;
    int rB = (lane & 7) + ((lane >> 4) << 3);
    int cB = (lane >> 3) & 1;
    #pragma unroll
    for (int ks = 0; ks < 2; ks++) {
        u32 afH[2][4], afL[2][4];
        #pragma unroll
        for (int mt = 0; mt < 2; mt++) {
            u32 off = swz((u32)((wm * 32 + mt * 16 + rA) * 64 + (2 * ks + cA) * 16));
            ldsm4(afH[mt], aH + off);
            ldsm4(afL[mt], aL + off);
        }
        #pragma unroll
        for (int nh = 0; nh < 2; nh++) {
            u32 bfH[2][4], bfL[2][4];
            #pragma unroll
            for (int q = 0; q < 2; q++) {
                u32 off = swz((u32)((wn * 64 + nh * 32 + q * 16 + rB) * 64 + (2 * ks + cB) * 16));
                ldsm4(bfH[q], bH + off);
                ldsm4(bfL[q], bL + off);
            }
            #pragma unroll
            for (int mt = 0; mt < 2; mt++)
                #pragma unroll
                for (int p = 0; p < 4; p++) {
                    int nt = nh * 4 + p;
                    u32 bh0 = bfH[p >> 1][(p & 1) * 2], bh1 = bfH[p >> 1][(p & 1) * 2 + 1];
                    u32 bl0 = bfL[p >> 1][(p & 1) * 2], bl1 = bfL[p >> 1][(p & 1) * 2 + 1];
                    mma(acc[mt][nt], afH[mt], bh0, bh1);
                    mma(acc[mt][nt], afH[mt], bl0, bl1);
                    mma(acc[mt][nt], afL[mt], bh0, bh1);
                }
        }
    }
}

// ---------------------------------------------------------------------------
// weight pre-split
// ---------------------------------------------------------------------------
__global__ void convert_Wh(const float* __restrict__ Wh) {
    int idx = blockIdx.x * blockDim.x + threadIdx.x;   // 512*512
    float v = Wh[idx];
    __nv_bfloat16 h = __float2bfloat16(v);
    __nv_bfloat16 l = __float2bfloat16(v - __bfloat162float(h));
    g_WhH[idx] = *reinterpret_cast<u16*>(&h);
    g_WhL[idx] = *reinterpret_cast<u16*>(&l);
}
__global__ void convert_Wx(const float* __restrict__ Wx) {
    int idx = blockIdx.x * blockDim.x + threadIdx.x;   // 512*256
    int n = idx >> 8, k = idx & 255;
    float v = Wx[k * 512 + n];
    __nv_bfloat16 h = __float2bfloat16(v);
    __nv_bfloat16 l = __float2bfloat16(v - __bfloat162float(h));
    g_WxH[idx] = *reinterpret_cast<u16*>(&h);
    g_WxL[idx] = *reinterpret_cast<u16*>(&l);
}

// ---------------------------------------------------------------------------
// C_k = W_m @ (A^k @ Bv)
// ---------------------------------------------------------------------------
__global__ void compute_C(const float* __restrict__ A, const float* __restrict__ Bv,
                          const float* __restrict__ Wm) {
    __shared__ float v[2][ORDER];
    int tid = threadIdx.x;
    if (tid < ORDER) v[0][tid] = Bv[tid];
    __syncthreads();
    int cur = 0;
    for (int k = 0; k < TSTEPS; ++k) {
        float c = 0.f;
        const float* wrow = Wm + (size_t)tid * ORDER;
        #pragma unroll 8
        for (int i = 0; i < ORDER; ++i) c = fmaf(wrow[i], v[cur][i], c);
        g_C[k * HIDDEN + tid] = c;
        float nv = 0.f;
        if (tid < ORDER) {
            const float* arow = A + (size_t)tid * ORDER;
            #pragma unroll 8
            for (int i = 0; i < ORDER; ++i) nv = fmaf(arow[i], v[cur][i], nv);
        }
        __syncthreads();
        if (tid < ORDER) v[1 - cur][tid] = nv;
        cur ^= 1;
        __syncthreads();
    }
}

// ---------------------------------------------------------------------------
// Fused: u[b,t] = x . e_x  AND  split X -> g_XH/g_XL.  One warp per row.
// ---------------------------------------------------------------------------
__global__ void convX_U(const float* __restrict__ X, const float* __restrict__ ex) {
    __shared__ float se[INPUT_DIM];
    int tid = threadIdx.x;
    if (tid < INPUT_DIM) se[tid] = ex[tid];
    __syncthreads();
    int warp = tid >> 5, lane = tid & 31;
    size_t r = (size_t)blockIdx.x * 8 + warp;
    const float* xr = X + r * INPUT_DIM + lane * 8;
    float4 v0 = *(const float4*)(xr);
    float4 v1 = *(const float4*)(xr + 4);
    const float* er = se + lane * 8;
    float s = v0.x * er[0] + v0.y * er[1] + v0.z * er[2] + v0.w * er[3]
            + v1.x * er[4] + v1.y * er[5] + v1.z * er[6] + v1.w * er[7];
    #pragma unroll
    for (int o = 16; o; o >>= 1) s += __shfl_xor_sync(0xffffffffu, s, o);
    if (lane == 0) g_U[r] = s;

    uint4 hi, lo;
    split2(v0.x, v0.y, hi.x, lo.x);
    split2(v0.z, v0.w, hi.y, lo.y);
    split2(v1.x, v1.y, hi.z, lo.z);
    split2(v1.z, v1.w, hi.w, lo.w);
    *(uint4*)(g_XH + r * INPUT_DIM + lane * 8) = hi;
    *(uint4*)(g_XL + r * INPUT_DIM + lane * 8) = lo;
}

// ---------------------------------------------------------------------------
// gemm_p: P = X @ Wx + triangular(U,C); rows with t==0 emit H_0 directly.
// grid (1472, 4), 256 threads.
// ---------------------------------------------------------------------------
extern __shared__ char dsm[];
__global__ void __launch_bounds__(256, 2) gemm_p_v2(float* __restrict__ out) {
    u32 sb = smem_u32(dsm);
    float* Cs = (float*)(dsm + 2 * STAGE_B);          // [23][128]
    float* sU = Cs + TSTEPS * 128;                    // [184]

    int tid = threadIdx.x, wid = tid >> 5, lane = tid & 31;
    int wm = wid & 3, wn = wid >> 2;
    int rowBase = blockIdx.x * 128, colBase = blockIdx.y * 128;
    int b0 = rowBase / TSTEPS;

    for (int i = tid; i < TSTEPS * 128; i += 256)
        Cs[i] = g_C[(i >> 7) * HIDDEN + colBase + (i & 127)];
    {
        int cnt = BATCH * TSTEPS - b0 * TSTEPS;
        if (cnt > 184) cnt = 184;
        for (int i = tid; i < cnt; i += 256) sU[i] = g_U[b0 * TSTEPS + i];
    }

    float acc[2][8][4];
    #pragma unroll
    for (int a = 0; a < 2; a++)
        #pragma unroll
        for (int b = 0; b < 8; b++)
            #pragma unroll
            for (int c = 0; c < 4; c++) acc[a][b][c] = 0.f;

    stage_load(sb, INPUT_DIM, g_XH, g_XL, rowBase, g_WxH, g_WxL, colBase, 0, tid);
    cp_commit();
    const int NCH = INPUT_DIM / KCH;   // 8
    for (int c = 0; c < NCH; c++) {
        if (c + 1 < NCH) {
            stage_load(sb + ((c + 1) & 1) * STAGE_B, INPUT_DIM, g_XH, g_XL, rowBase,
                       g_WxH, g_WxL, colBase, (c + 1) * KCH, tid);
            cp_commit();
            cp_wait1();
        } else {
            cp_wait0();
        }
        __syncthreads();
        stage_compute(sb + (c & 1) * STAGE_B, acc, wm, wn, lane);
        __syncthreads();
    }

    int quad = lane >> 2, tq = lane & 3;
    #pragma unroll
    for (int mt = 0; mt < 2; mt++) {
        #pragma unroll
        for (int h = 0; h < 2; h++) {
            int r = rowBase + wm * 32 + mt * 16 + quad + h * 8;
            int bb = r / TSTEPS;
            int tr = r - bb * TSTEPS;
            const float* u = sU + (bb - b0) * TSTEPS;
            #pragma unroll
            for (int nt = 0; nt < 8; nt++) {
                int cc = wn * 64 + nt * 8 + tq * 2;
                float v0 = acc[mt][nt][h * 2];
                float v1 = acc[mt][nt][h * 2 + 1];
                for (int s = 0; s <= tr; ++s) {
                    float us = u[s];
                    const float* cp = Cs + (tr - s) * 128 + cc;
                    v0 = fmaf(us, cp[0], v0);
                    v1 = fmaf(us, cp[1], v1);
                }
                size_t off = (size_t)r * HIDDEN + colBase + cc;
                if (tr == 0) {
                    float h0 = v0 >= 0.f ? v0 : SLOPE * v0;
                    float h1 = v1 >= 0.f ? v1 : SLOPE * v1;
                    *(float2*)(out + off) = make_float2(h0, h1);
                    u32 hi, lo;
                    split2(h0, h1, hi, lo);
                    size_t hoff = (size_t)bb * HIDDEN + colBase + cc;
                    *(u32*)(g_HH0 + hoff) = hi;
                    *(u32*)(g_HL0 + hoff) = lo;
                } else {
                    *(float2*)(g_P + off) = make_float2(v0, v1);
                }
            }
        }
    }
}

// ---------------------------------------------------------------------------
// gemm_h: H_t = lrelu(P_t + H_{t-1} @ Wh^T).  grid (64, 4), 256 threads.
// par selects ping-pong split buffers: read buf[par], write buf[par^1].
// ---------------------------------------------------------------------------
__global__ void __launch_bounds__(256, 2) gemm_h_v2(float* __restrict__ out, int t, int par) {
    u32 sb = smem_u32(dsm);
    int tid = threadIdx.x, wid = tid >> 5, lane = tid & 31;
    int wm = wid & 3, wn = wid >> 2;
    int rowBase = blockIdx.x * 128, colBase = blockIdx.y * 128;

    const u16* AH = par ? g_HH1 : g_HH0;
    const u16* AL = par ? g_HL1 : g_HL0;
    u16* DH = par ? g_HH0 : g_HH1;
    u16* DL = par ? g_HL0 : g_HL1;

    float acc[2][8][4];
    #pragma unroll
    for (int a = 0; a < 2; a++)
        #pragma unroll
        for (int b = 0; b < 8; b++)
            #pragma unroll
            for (int c = 0; c < 4; c++) acc[a][b][c] = 0.f;

    stage_load(sb, HIDDEN, AH, AL, rowBase, g_WhH, g_WhL, colBase, 0, tid);
    cp_commit();
    const int NCH = HIDDEN / KCH;   // 16
    for (int c = 0; c < NCH; c++) {
        if (c + 1 < NCH) {
            stage_load(sb + ((c + 1) & 1) * STAGE_B, HIDDEN, AH, AL, rowBase,
                       g_WhH, g_WhL, colBase, (c + 1) * KCH, tid);
            cp_commit();
            cp_wait1();
        } else {
            cp_wait0();
        }
        __syncthreads();
        stage_compute(sb + (c & 1) * STAGE_B, acc, wm, wn, lane);
        __syncthreads();
    }

    int quad = lane >> 2, tq = lane & 3;
    #pragma unroll
    for (int mt = 0; mt < 2; mt++) {
        #pragma unroll
        for (int h = 0; h < 2; h++) {
            int m = rowBase + wm * 32 + mt * 16 + quad + h * 8;
            size_t off0 = ((size_t)m * TSTEPS + t) * HIDDEN + colBase;
            size_t hoff0 = (size_t)m * HIDDEN + colBase;
            #pragma unroll
            for (int nt = 0; nt < 8; nt++) {
                int cc = wn * 64 + nt * 8 + tq * 2;
                float2 p = *(const float2*)(g_P + off0 + cc);
                float v0 = acc[mt][nt][h * 2] + p.x;
                float v1 = acc[mt][nt][h * 2 + 1] + p.y;
                v0 = v0 >= 0.f ? v0 : SLOPE * v0;
                v1 = v1 >= 0.f ? v1 : SLOPE * v1;
                *(float2*)(out + off0 + cc) = make_float2(v0, v1);
                u32 hi, lo;
                split2(v0, v1, hi, lo);
                *(u32*)(DH + hoff0 + cc) = hi;
                *(u32*)(DL + hoff0 + cc) = lo;
            }
        }
    }
}

// ---------------------------------------------------------------------------
extern "C" void kernel_launch(void* const* d_in, const int* in_sizes, int n_in,
                              void* d_out, int out_size) {
    const float* X  = (const float*)d_in[0];
    const float* A  = (const float*)d_in[1];
    const float* Bv = (const float*)d_in[2];
    const float* Wh = (const float*)d_in[3];
    const float* Wm = (const float*)d_in[4];
    const float* Wx = (const float*)d_in[5];
    const float* ex = (const float*)d_in[6];
    float* out = (float*)d_out;

    cudaFuncSetAttribute(gemm_p_v2, cudaFuncAttributeMaxDynamicSharedMemorySize, SMEM_P);
    cudaFuncSetAttribute(gemm_h_v2, cudaFuncAttributeMaxDynamicSharedMemorySize, SMEM_H);

    convert_Wh<<<1024, 256>>>(Wh);
    convert_Wx<<<512, 256>>>(Wx);
    compute_C<<<1, 512>>>(A, Bv, Wm);
    convX_U<<<(BATCH * TSTEPS) / 8, 256>>>(X, ex);

    dim3 gp((BATCH * TSTEPS) / 128, HIDDEN / 128);
    gemm_p_v2<<<gp, 256, SMEM_P>>>(out);

    dim3 gh(BATCH / 128, HIDDEN / 128);
    for (int t = 1; t < TSTEPS; ++t)
        gemm_h_v2<<<gh, 256, SMEM_H>>>(out, t, (t - 1) & 1);
}

// round 7
// speedup vs baseline: 1.6701x; 1.0861x over previous
#include <cuda_runtime.h>
#include <cuda_fp16.h>
#include <cstdint>

typedef unsigned short u16;
typedef unsigned int u32;

#define ORDER 256
#define HIDDEN 512
#define INPUT_DIM 256
#define BATCH 8192
#define TSTEPS 23
#define SLOPE 0.2f

#define KCH 32                      // K per pipeline chunk
#define OPER_B (128 * 64)           // 8 KB per operand tile (128 rows x 64B)
#define STAGE_B (3 * OPER_B)        // A, BH, BL = 24 KB
#define NSTAGE 3
#define SMEM_H (NSTAGE * STAGE_B)                              // 72 KB
#define SMEM_P (NSTAGE * STAGE_B + TSTEPS * 128 * 4 + 184 * 4) // +Cs +U

// ---------------- scratch ----------------
__device__ float g_C[TSTEPS * HIDDEN];
__device__ float g_U[BATCH * TSTEPS];
__device__ float g_P[(size_t)BATCH * TSTEPS * HIDDEN];
__device__ __align__(16) u16 g_WhH[512 * 512];   // fp16 hi, [n][k]
__device__ __align__(16) u16 g_WhL[512 * 512];   // fp16 lo
__device__ __align__(16) u16 g_WxH[512 * 256];   // fp16 hi, [n][k] = Wx[k][n]
__device__ __align__(16) u16 g_WxL[512 * 256];
__device__ __align__(16) u16 g_Xf[(size_t)BATCH * TSTEPS * 256];  // fp16 X
__device__ __align__(16) u16 g_Hf0[BATCH * 512];                  // fp16 H ping
__device__ __align__(16) u16 g_Hf1[BATCH * 512];                  // fp16 H pong

// ---------------- low-level helpers ----------------
__device__ __forceinline__ u32 smem_u32(const void* p) {
    u32 a;
    asm("{ .reg .u64 t; cvta.to.shared.u64 t, %1; cvt.u32.u64 %0, t; }" : "=r"(a) : "l"(p));
    return a;
}
__device__ __forceinline__ u32 swz(u32 off) { return off ^ ((off >> 3) & 0x30); }

__device__ __forceinline__ void cp16(u32 dst, const void* src) {
    asm volatile("cp.async.cg.shared.global [%0], [%1], 16;" :: "r"(dst), "l"(src));
}
__device__ __forceinline__ void cp_commit() { asm volatile("cp.async.commit_group;" ::: "memory"); }
__device__ __forceinline__ void cp_wait1() { asm volatile("cp.async.wait_group 1;" ::: "memory"); }

__device__ __forceinline__ void ldsm4(u32* r, u32 a) {
    asm volatile("ldmatrix.sync.aligned.m8n8.x4.shared.b16 {%0,%1,%2,%3}, [%4];"
                 : "=r"(r[0]), "=r"(r[1]), "=r"(r[2]), "=r"(r[3]) : "r"(a));
}
__device__ __forceinline__ void mma(float* d, const u32* a, u32 b0, u32 b1) {
    asm volatile(
        "mma.sync.aligned.m16n8k16.row.col.f32.f16.f16.f32 "
        "{%0,%1,%2,%3},{%4,%5,%6,%7},{%8,%9},{%0,%1,%2,%3};\n"
        : "+f"(d[0]), "+f"(d[1]), "+f"(d[2]), "+f"(d[3])
        : "r"(a[0]), "r"(a[1]), "r"(a[2]), "r"(a[3]), "r"(b0), "r"(b1));
}
__device__ __forceinline__ u32 pack_h2(float x0, float x1) {
    __half2 h = __floats2half2_rn(x0, x1);
    return *reinterpret_cast<u32*>(&h);
}

// ---------------- stage loader: 6 cp16 per thread ----------------
__device__ __forceinline__ void stage_load(u32 sbase, int kdim,
                                           const u16* __restrict__ A, size_t aRowBase,
                                           const u16* __restrict__ BH, const u16* __restrict__ BL,
                                           int colBase, int k0, int tid) {
    #pragma unroll
    for (int j = 0; j < 2; j++) {
        int idx = j * 256 + tid;
        int row = idx >> 2, c = idx & 3;
        u32 d = sbase + swz((u32)(row * 64 + c * 16));
        cp16(d, A + (aRowBase + row) * kdim + k0 + c * 8);
    }
    #pragma unroll
    for (int j = 0; j < 2; j++) {
        int idx = j * 256 + tid;
        int row = idx >> 2, c = idx & 3;
        u32 d = sbase + OPER_B + swz((u32)(row * 64 + c * 16));
        size_t gi = (size_t)(colBase + row) * kdim + k0 + c * 8;
        cp16(d, BH + gi);
        cp16(d + OPER_B, BL + gi);
    }
}

// ---------------- stage compute: 64 HMMA per warp ----------------
__device__ __forceinline__ void stage_compute(u32 sbase, float acc[2][8][4],
                                              int wm, int wn, int lane) {
    u32 aB = sbase, bHB = sbase + OPER_B, bLB = sbase + 2 * OPER_B;
    int rA = (lane & 7) + ((lane >> 3) & 1) * 8;
    int cA = lane >> 4;
    int rB = (lane & 7) + ((lane >> 4) << 3);
    int cB = (lane >> 3) & 1;
    #pragma unroll
    for (int ks = 0; ks < 2; ks++) {
        u32 af[2][4];
        #pragma unroll
        for (int mt = 0; mt < 2; mt++) {
            u32 off = swz((u32)((wm * 32 + mt * 16 + rA) * 64 + (2 * ks + cA) * 16));
            ldsm4(af[mt], aB + off);
        }
        #pragma unroll
        for (int nh = 0; nh < 2; nh++) {
            u32 bfH[2][4], bfL[2][4];
            #pragma unroll
            for (int q = 0; q < 2; q++) {
                u32 off = swz((u32)((wn * 64 + nh * 32 + q * 16 + rB) * 64 + (2 * ks + cB) * 16));
                ldsm4(bfH[q], bHB + off);
                ldsm4(bfL[q], bLB + off);
            }
            #pragma unroll
            for (int mt = 0; mt < 2; mt++)
                #pragma unroll
                for (int p = 0; p < 4; p++) {
                    int nt = nh * 4 + p;
                    mma(acc[mt][nt], af[mt], bfH[p >> 1][(p & 1) * 2], bfH[p >> 1][(p & 1) * 2 + 1]);
                    mma(acc[mt][nt], af[mt], bfL[p >> 1][(p & 1) * 2], bfL[p >> 1][(p & 1) * 2 + 1]);
                }
        }
    }
}

// ---------------------------------------------------------------------------
// weight pre-split (fp16 hi/lo)
// ---------------------------------------------------------------------------
__global__ void convert_Wh(const float* __restrict__ Wh) {
    int idx = blockIdx.x * blockDim.x + threadIdx.x;   // 512*512
    float v = Wh[idx];
    __half h = __float2half_rn(v);
    __half l = __float2half_rn(v - __half2float(h));
    g_WhH[idx] = *reinterpret_cast<u16*>(&h);
    g_WhL[idx] = *reinterpret_cast<u16*>(&l);
}
__global__ void convert_Wx(const float* __restrict__ Wx) {
    int idx = blockIdx.x * blockDim.x + threadIdx.x;   // 512*256
    int n = idx >> 8, k = idx & 255;
    float v = Wx[k * 512 + n];
    __half h = __float2half_rn(v);
    __half l = __float2half_rn(v - __half2float(h));
    g_WxH[idx] = *reinterpret_cast<u16*>(&h);
    g_WxL[idx] = *reinterpret_cast<u16*>(&l);
}

// ---------------------------------------------------------------------------
// C_k = W_m @ (A^k @ Bv)
// ---------------------------------------------------------------------------
__global__ void compute_C(const float* __restrict__ A, const float* __restrict__ Bv,
                          const float* __restrict__ Wm) {
    __shared__ float v[2][ORDER];
    int tid = threadIdx.x;
    if (tid < ORDER) v[0][tid] = Bv[tid];
    __syncthreads();
    int cur = 0;
    for (int k = 0; k < TSTEPS; ++k) {
        float c = 0.f;
        const float* wrow = Wm + (size_t)tid * ORDER;
        #pragma unroll 8
        for (int i = 0; i < ORDER; ++i) c = fmaf(wrow[i], v[cur][i], c);
        g_C[k * HIDDEN + tid] = c;
        float nv = 0.f;
        if (tid < ORDER) {
            const float* arow = A + (size_t)tid * ORDER;
            #pragma unroll 8
            for (int i = 0; i < ORDER; ++i) nv = fmaf(arow[i], v[cur][i], nv);
        }
        __syncthreads();
        if (tid < ORDER) v[1 - cur][tid] = nv;
        cur ^= 1;
        __syncthreads();
    }
}

// ---------------------------------------------------------------------------
// Fused: u = x . e_x  AND  convert X -> fp16.  One warp per row.
// ---------------------------------------------------------------------------
__global__ void convX_U(const float* __restrict__ X, const float* __restrict__ ex) {
    __shared__ float se[INPUT_DIM];
    int tid = threadIdx.x;
    if (tid < INPUT_DIM) se[tid] = ex[tid];
    __syncthreads();
    int warp = tid >> 5, lane = tid & 31;
    size_t r = (size_t)blockIdx.x * 8 + warp;
    const float* xr = X + r * INPUT_DIM + lane * 8;
    float4 v0 = *(const float4*)(xr);
    float4 v1 = *(const float4*)(xr + 4);
    const float* er = se + lane * 8;
    float s = v0.x * er[0] + v0.y * er[1] + v0.z * er[2] + v0.w * er[3]
            + v1.x * er[4] + v1.y * er[5] + v1.z * er[6] + v1.w * er[7];
    #pragma unroll
    for (int o = 16; o; o >>= 1) s += __shfl_xor_sync(0xffffffffu, s, o);
    if (lane == 0) g_U[r] = s;

    uint4 h;
    h.x = pack_h2(v0.x, v0.y);
    h.y = pack_h2(v0.z, v0.w);
    h.z = pack_h2(v1.x, v1.y);
    h.w = pack_h2(v1.z, v1.w);
    *(uint4*)(g_Xf + r * INPUT_DIM + lane * 8) = h;
}

// ---------------------------------------------------------------------------
// gemm_p: P = X @ Wx + triangular(U,C); rows with t==0 emit H_0.
// grid (1472, 4), 256 threads, 3-stage pipeline.
// ---------------------------------------------------------------------------
extern __shared__ char dsm[];
__global__ void __launch_bounds__(256, 2) gemm_p_v3(float* __restrict__ out) {
    u32 sb = smem_u32(dsm);
    float* Cs = (float*)(dsm + NSTAGE * STAGE_B);     // [23][128]
    float* sU = Cs + TSTEPS * 128;                    // [184]

    int tid = threadIdx.x, wid = tid >> 5, lane = tid & 31;
    int wm = wid & 3, wn = wid >> 2;
    int rowBase = blockIdx.x * 128, colBase = blockIdx.y * 128;
    int b0 = rowBase / TSTEPS;

    for (int i = tid; i < TSTEPS * 128; i += 256)
        Cs[i] = g_C[(i >> 7) * HIDDEN + colBase + (i & 127)];
    {
        int cnt = BATCH * TSTEPS - b0 * TSTEPS;
        if (cnt > 184) cnt = 184;
        for (int i = tid; i < cnt; i += 256) sU[i] = g_U[b0 * TSTEPS + i];
    }

    float acc[2][8][4];
    #pragma unroll
    for (int a = 0; a < 2; a++)
        #pragma unroll
        for (int b = 0; b < 8; b++)
            #pragma unroll
            for (int c = 0; c < 4; c++) acc[a][b][c] = 0.f;

    const int NCH = INPUT_DIM / KCH;   // 8
    stage_load(sb, INPUT_DIM, g_Xf, rowBase, g_WxH, g_WxL, colBase, 0, tid);
    cp_commit();
    stage_load(sb + STAGE_B, INPUT_DIM, g_Xf, rowBase, g_WxH, g_WxL, colBase, KCH, tid);
    cp_commit();

    int buf = 0;
    for (int c = 0; c < NCH; c++) {
        cp_wait1();
        __syncthreads();
        if (c + 2 < NCH) {
            int nb = buf + 2; if (nb >= NSTAGE) nb -= NSTAGE;
            stage_load(sb + nb * STAGE_B, INPUT_DIM, g_Xf, rowBase,
                       g_WxH, g_WxL, colBase, (c + 2) * KCH, tid);
        }
        cp_commit();
        stage_compute(sb + buf * STAGE_B, acc, wm, wn, lane);
        if (++buf == NSTAGE) buf = 0;
    }

    int quad = lane >> 2, tq = lane & 3;
    #pragma unroll
    for (int mt = 0; mt < 2; mt++) {
        #pragma unroll
        for (int h = 0; h < 2; h++) {
            int r = rowBase + wm * 32 + mt * 16 + quad + h * 8;
            int bb = r / TSTEPS;
            int tr = r - bb * TSTEPS;
            const float* u = sU + (bb - b0) * TSTEPS;
            #pragma unroll
            for (int nt = 0; nt < 8; nt++) {
                int cc = wn * 64 + nt * 8 + tq * 2;
                float v0 = acc[mt][nt][h * 2];
                float v1 = acc[mt][nt][h * 2 + 1];
                for (int s = 0; s <= tr; ++s) {
                    float us = u[s];
                    const float* cp = Cs + (tr - s) * 128 + cc;
                    v0 = fmaf(us, cp[0], v0);
                    v1 = fmaf(us, cp[1], v1);
                }
                size_t off = (size_t)r * HIDDEN + colBase + cc;
                if (tr == 0) {
                    float h0 = v0 >= 0.f ? v0 : SLOPE * v0;
                    float h1 = v1 >= 0.f ? v1 : SLOPE * v1;
                    *(float2*)(out + off) = make_float2(h0, h1);
                    *(u32*)(g_Hf0 + (size_t)bb * HIDDEN + colBase + cc) = pack_h2(h0, h1);
                } else {
                    *(float2*)(g_P + off) = make_float2(v0, v1);
                }
            }
        }
    }
}

// ---------------------------------------------------------------------------
// gemm_h: H_t = lrelu(P_t + H_{t-1} @ Wh^T).  grid (64, 4), 256 threads.
// ---------------------------------------------------------------------------
__global__ void __launch_bounds__(256, 2) gemm_h_v3(float* __restrict__ out, int t, int par) {
    u32 sb = smem_u32(dsm);
    int tid = threadIdx.x, wid = tid >> 5, lane = tid & 31;
    int wm = wid & 3, wn = wid >> 2;
    int rowBase = blockIdx.x * 128, colBase = blockIdx.y * 128;

    const u16* Af = par ? g_Hf1 : g_Hf0;
    u16* Df = par ? g_Hf0 : g_Hf1;

    float acc[2][8][4];
    #pragma unroll
    for (int a = 0; a < 2; a++)
        #pragma unroll
        for (int b = 0; b < 8; b++)
            #pragma unroll
            for (int c = 0; c < 4; c++) acc[a][b][c] = 0.f;

    const int NCH = HIDDEN / KCH;   // 16
    stage_load(sb, HIDDEN, Af, rowBase, g_WhH, g_WhL, colBase, 0, tid);
    cp_commit();
    stage_load(sb + STAGE_B, HIDDEN, Af, rowBase, g_WhH, g_WhL, colBase, KCH, tid);
    cp_commit();

    int buf = 0;
    for (int c = 0; c < NCH; c++) {
        cp_wait1();
        __syncthreads();
        if (c + 2 < NCH) {
            int nb = buf + 2; if (nb >= NSTAGE) nb -= NSTAGE;
            stage_load(sb + nb * STAGE_B, HIDDEN, Af, rowBase,
                       g_WhH, g_WhL, colBase, (c + 2) * KCH, tid);
        }
        cp_commit();
        stage_compute(sb + buf * STAGE_B, acc, wm, wn, lane);
        if (++buf == NSTAGE) buf = 0;
    }

    int quad = lane >> 2, tq = lane & 3;
    #pragma unroll
    for (int mt = 0; mt < 2; mt++) {
        #pragma unroll
        for (int h = 0; h < 2; h++) {
            int m = rowBase + wm * 32 + mt * 16 + quad + h * 8;
            size_t off0 = ((size_t)m * TSTEPS + t) * HIDDEN + colBase;
            size_t hoff0 = (size_t)m * HIDDEN + colBase;
            #pragma unroll
            for (int nt = 0; nt < 8; nt++) {
                int cc = wn * 64 + nt * 8 + tq * 2;
                float2 p = *(const float2*)(g_P + off0 + cc);
                float v0 = acc[mt][nt][h * 2] + p.x;
                float v1 = acc[mt][nt][h * 2 + 1] + p.y;
                v0 = v0 >= 0.f ? v0 : SLOPE * v0;
                v1 = v1 >= 0.f ? v1 : SLOPE * v1;
                *(float2*)(out + off0 + cc) = make_float2(v0, v1);
                *(u32*)(Df + hoff0 + cc) = pack_h2(v0, v1);
            }
        }
    }
}

// ---------------------------------------------------------------------------
extern "C" void kernel_launch(void* const* d_in, const int* in_sizes, int n_in,
                              void* d_out, int out_size) {
    const float* X  = (const float*)d_in[0];
    const float* A  = (const float*)d_in[1];
    const float* Bv = (const float*)d_in[2];
    const float* Wh = (const float*)d_in[3];
    const float* Wm = (const float*)d_in[4];
    const float* Wx = (const float*)d_in[5];
    const float* ex = (const float*)d_in[6];
    float* out = (float*)d_out;

    cudaFuncSetAttribute(gemm_p_v3, cudaFuncAttributeMaxDynamicSharedMemorySize, SMEM_P);
    cudaFuncSetAttribute(gemm_h_v3, cudaFuncAttributeMaxDynamicSharedMemorySize, SMEM_H);

    convert_Wh<<<1024, 256>>>(Wh);
    convert_Wx<<<512, 256>>>(Wx);
    compute_C<<<1, 512>>>(A, Bv, Wm);
    convX_U<<<(BATCH * TSTEPS) / 8, 256>>>(X, ex);

    dim3 gp((BATCH * TSTEPS) / 128, HIDDEN / 128);
    gemm_p_v3<<<gp, 256, SMEM_P>>>(out);

    dim3 gh(BATCH / 128, HIDDEN / 128);
    for (int t = 1; t < TSTEPS; ++t)
        gemm_h_v3<<<gh, 256, SMEM_H>>>(out, t, (t - 1) & 1);
}

// round 8
// speedup vs baseline: 1.6810x; 1.0065x over previous
#include <cuda_runtime.h>
#include <cuda_fp16.h>
#include <cstdint>

typedef unsigned short u16;
typedef unsigned int u32;

#define ORDER 256
#define HIDDEN 512
#define INPUT_DIM 256
#define BATCH 8192
#define TSTEPS 23
#define SLOPE 0.2f

#define KCH 32                      // K per pipeline chunk
#define OPER_B (128 * 64)           // 8 KB per operand tile (128 rows x 64B)
#define NSTAGE 3
#define STAGE_H (3 * OPER_B)        // gemm_h: A, BH, BL = 24 KB
#define STAGE_P (2 * OPER_B)        // gemm_p: A, BH     = 16 KB
#define SMEM_H (NSTAGE * STAGE_H)                              // 72 KB
#define SMEM_P (NSTAGE * STAGE_P + TSTEPS * 128 * 4 + 184 * 4) // ~60 KB

// ---------------- scratch ----------------
__device__ float g_C[TSTEPS * HIDDEN];
__device__ float g_U[BATCH * TSTEPS];
__device__ float g_P[(size_t)BATCH * TSTEPS * HIDDEN];
__device__ __align__(16) u16 g_WhH[512 * 512];   // fp16 hi, [n][k]
__device__ __align__(16) u16 g_WhL[512 * 512];   // fp16 lo
__device__ __align__(16) u16 g_WxH[512 * 256];   // fp16 hi, [n][k] = Wx[k][n]
__device__ __align__(16) u16 g_Xf[(size_t)BATCH * TSTEPS * 256];  // fp16 X
__device__ __align__(16) u16 g_Hf0[BATCH * 512];                  // fp16 H ping
__device__ __align__(16) u16 g_Hf1[BATCH * 512];                  // fp16 H pong

// ---------------- low-level helpers ----------------
__device__ __forceinline__ u32 smem_u32(const void* p) {
    u32 a;
    asm("{ .reg .u64 t; cvta.to.shared.u64 t, %1; cvt.u32.u64 %0, t; }" : "=r"(a) : "l"(p));
    return a;
}
__device__ __forceinline__ u32 swz(u32 off) { return off ^ ((off >> 3) & 0x30); }

__device__ __forceinline__ void cp16(u32 dst, const void* src) {
    asm volatile("cp.async.cg.shared.global [%0], [%1], 16;" :: "r"(dst), "l"(src));
}
__device__ __forceinline__ void cp_commit() { asm volatile("cp.async.commit_group;" ::: "memory"); }
__device__ __forceinline__ void cp_wait1() { asm volatile("cp.async.wait_group 1;" ::: "memory"); }

__device__ __forceinline__ void ldsm4(u32* r, u32 a) {
    asm volatile("ldmatrix.sync.aligned.m8n8.x4.shared.b16 {%0,%1,%2,%3}, [%4];"
                 : "=r"(r[0]), "=r"(r[1]), "=r"(r[2]), "=r"(r[3]) : "r"(a));
}
// fp32-accumulate HMMA
__device__ __forceinline__ void mma_f32(float* d, const u32* a, u32 b0, u32 b1) {
    asm volatile(
        "mma.sync.aligned.m16n8k16.row.col.f32.f16.f16.f32 "
        "{%0,%1,%2,%3},{%4,%5,%6,%7},{%8,%9},{%0,%1,%2,%3};\n"
        : "+f"(d[0]), "+f"(d[1]), "+f"(d[2]), "+f"(d[3])
        : "r"(a[0]), "r"(a[1]), "r"(a[2]), "r"(a[3]), "r"(b0), "r"(b1));
}
// fp16-accumulate HMMA (lo-term: magnitude ~2^-11 of main, acc error negligible)
__device__ __forceinline__ void mma_f16(u32* d, const u32* a, u32 b0, u32 b1) {
    asm volatile(
        "mma.sync.aligned.m16n8k16.row.col.f16.f16.f16.f16 "
        "{%0,%1},{%2,%3,%4,%5},{%6,%7},{%0,%1};\n"
        : "+r"(d[0]), "+r"(d[1])
        : "r"(a[0]), "r"(a[1]), "r"(a[2]), "r"(a[3]), "r"(b0), "r"(b1));
}
__device__ __forceinline__ u32 pack_h2(float x0, float x1) {
    __half2 h = __floats2half2_rn(x0, x1);
    return *reinterpret_cast<u32*>(&h);
}

// ---------------- stage loaders ----------------
// gemm_h: A(fp16 H) + BH + BL  (6 cp16 / thread)
__device__ __forceinline__ void stage_load_h(u32 sbase,
                                             const u16* __restrict__ A, size_t aRowBase,
                                             int colBase, int k0, int tid) {
    #pragma unroll
    for (int j = 0; j < 2; j++) {
        int idx = j * 256 + tid;
        int row = idx >> 2, c = idx & 3;
        u32 d = sbase + swz((u32)(row * 64 + c * 16));
        cp16(d, A + (aRowBase + row) * HIDDEN + k0 + c * 8);
        size_t gi = (size_t)(colBase + row) * HIDDEN + k0 + c * 8;
        cp16(d + OPER_B, g_WhH + gi);
        cp16(d + 2 * OPER_B, g_WhL + gi);
    }
}
// gemm_p: A(fp16 X) + BH only  (4 cp16 / thread)
__device__ __forceinline__ void stage_load_p(u32 sbase, size_t aRowBase,
                                             int colBase, int k0, int tid) {
    #pragma unroll
    for (int j = 0; j < 2; j++) {
        int idx = j * 256 + tid;
        int row = idx >> 2, c = idx & 3;
        u32 d = sbase + swz((u32)(row * 64 + c * 16));
        cp16(d, g_Xf + (aRowBase + row) * INPUT_DIM + k0 + c * 8);
        cp16(d + OPER_B, g_WxH + (size_t)(colBase + row) * INPUT_DIM + k0 + c * 8);
    }
}

// ---------------- gemm_h chunk compute: 32 f32-acc + 32 f16-acc HMMA / warp ----
__device__ __forceinline__ void compute_h(u32 sbase, float accH[2][8][4], u32 accL[2][8][2],
                                          int wm, int wn, int lane) {
    u32 aB = sbase, bHB = sbase + OPER_B, bLB = sbase + 2 * OPER_B;
    int rA = (lane & 7) + ((lane >> 3) & 1) * 8;
    int cA = lane >> 4;
    int rB = (lane & 7) + ((lane >> 4) << 3);
    int cB = (lane >> 3) & 1;
    #pragma unroll
    for (int ks = 0; ks < 2; ks++) {
        u32 af[2][4];
        #pragma unroll
        for (int mt = 0; mt < 2; mt++) {
            u32 off = swz((u32)((wm * 32 + mt * 16 + rA) * 64 + (2 * ks + cA) * 16));
            ldsm4(af[mt], aB + off);
        }
        #pragma unroll
        for (int nh = 0; nh < 2; nh++) {
            #pragma unroll
            for (int q = 0; q < 2; q++) {
                u32 bfH[4], bfL[4];
                u32 off = swz((u32)((wn * 64 + nh * 32 + q * 16 + rB) * 64 + (2 * ks + cB) * 16));
                ldsm4(bfH, bHB + off);
                ldsm4(bfL, bLB + off);
                #pragma unroll
                for (int pb = 0; pb < 2; pb++) {
                    int nt = nh * 4 + q * 2 + pb;
                    #pragma unroll
                    for (int mt = 0; mt < 2; mt++) {
                        mma_f32(accH[mt][nt], af[mt], bfH[pb * 2], bfH[pb * 2 + 1]);
                        mma_f16(accL[mt][nt], af[mt], bfL[pb * 2], bfL[pb * 2 + 1]);
                    }
                }
            }
        }
    }
}

// ---------------- gemm_p chunk compute: 32 f32-acc HMMA / warp -----------------
__device__ __forceinline__ void compute_p(u32 sbase, float accH[2][8][4],
                                          int wm, int wn, int lane) {
    u32 aB = sbase, bHB = sbase + OPER_B;
    int rA = (lane & 7) + ((lane >> 3) & 1) * 8;
    int cA = lane >> 4;
    int rB = (lane & 7) + ((lane >> 4) << 3);
    int cB = (lane >> 3) & 1;
    #pragma unroll
    for (int ks = 0; ks < 2; ks++) {
        u32 af[2][4];
        #pragma unroll
        for (int mt = 0; mt < 2; mt++) {
            u32 off = swz((u32)((wm * 32 + mt * 16 + rA) * 64 + (2 * ks + cA) * 16));
            ldsm4(af[mt], aB + off);
        }
        #pragma unroll
        for (int nh = 0; nh < 2; nh++) {
            #pragma unroll
            for (int q = 0; q < 2; q++) {
                u32 bfH[4];
                u32 off = swz((u32)((wn * 64 + nh * 32 + q * 16 + rB) * 64 + (2 * ks + cB) * 16));
                ldsm4(bfH, bHB + off);
                #pragma unroll
                for (int pb = 0; pb < 2; pb++) {
                    int nt = nh * 4 + q * 2 + pb;
                    #pragma unroll
                    for (int mt = 0; mt < 2; mt++)
                        mma_f32(accH[mt][nt], af[mt], bfH[pb * 2], bfH[pb * 2 + 1]);
                }
            }
        }
    }
}

// ---------------------------------------------------------------------------
// Fused: u = x . e_x  AND  convert X -> fp16.  One warp per row. (launched 1st)
// ---------------------------------------------------------------------------
__global__ void convX_U(const float* __restrict__ X, const float* __restrict__ ex) {
    __shared__ float se[INPUT_DIM];
    int tid = threadIdx.x;
    if (tid < INPUT_DIM) se[tid] = ex[tid];
    __syncthreads();
    int warp = tid >> 5, lane = tid & 31;
    size_t r = (size_t)blockIdx.x * 8 + warp;
    const float* xr = X + r * INPUT_DIM + lane * 8;
    float4 v0 = *(const float4*)(xr);
    float4 v1 = *(const float4*)(xr + 4);
    const float* er = se + lane * 8;
    float s = v0.x * er[0] + v0.y * er[1] + v0.z * er[2] + v0.w * er[3]
            + v1.x * er[4] + v1.y * er[5] + v1.z * er[6] + v1.w * er[7];
    #pragma unroll
    for (int o = 16; o; o >>= 1) s += __shfl_xor_sync(0xffffffffu, s, o);
    if (lane == 0) g_U[r] = s;

    uint4 h;
    h.x = pack_h2(v0.x, v0.y);
    h.y = pack_h2(v0.z, v0.w);
    h.z = pack_h2(v1.x, v1.y);
    h.w = pack_h2(v1.z, v1.w);
    *(uint4*)(g_Xf + r * INPUT_DIM + lane * 8) = h;
}

// ---------------------------------------------------------------------------
// weight pre-split
// ---------------------------------------------------------------------------
__global__ void convert_Wh(const float* __restrict__ Wh) {
    int idx = blockIdx.x * blockDim.x + threadIdx.x;   // 512*512
    float v = Wh[idx];
    __half h = __float2half_rn(v);
    __half l = __float2half_rn(v - __half2float(h));
    g_WhH[idx] = *reinterpret_cast<u16*>(&h);
    g_WhL[idx] = *reinterpret_cast<u16*>(&l);
}
__global__ void convert_Wx(const float* __restrict__ Wx) {
    int idx = blockIdx.x * blockDim.x + threadIdx.x;   // 512*256
    int n = idx >> 8, k = idx & 255;
    __half h = __float2half_rn(Wx[k * 512 + n]);
    g_WxH[idx] = *reinterpret_cast<u16*>(&h);
}

// ---------------------------------------------------------------------------
// C_k = W_m @ (A^k @ Bv)
// ---------------------------------------------------------------------------
__global__ void compute_C(const float* __restrict__ A, const float* __restrict__ Bv,
                          const float* __restrict__ Wm) {
    __shared__ float v[2][ORDER];
    int tid = threadIdx.x;
    if (tid < ORDER) v[0][tid] = Bv[tid];
    __syncthreads();
    int cur = 0;
    for (int k = 0; k < TSTEPS; ++k) {
        float c = 0.f;
        const float* wrow = Wm + (size_t)tid * ORDER;
        #pragma unroll 8
        for (int i = 0; i < ORDER; ++i) c = fmaf(wrow[i], v[cur][i], c);
        g_C[k * HIDDEN + tid] = c;
        float nv = 0.f;
        if (tid < ORDER) {
            const float* arow = A + (size_t)tid * ORDER;
            #pragma unroll 8
            for (int i = 0; i < ORDER; ++i) nv = fmaf(arow[i], v[cur][i], nv);
        }
        __syncthreads();
        if (tid < ORDER) v[1 - cur][tid] = nv;
        cur ^= 1;
        __syncthreads();
    }
}

// ---------------------------------------------------------------------------
// gemm_p: P = X @ WxH + triangular(U,C); rows with t==0 emit H_0.
// grid (1472, 4), 256 threads, 3-stage pipeline, 1-term.
// ---------------------------------------------------------------------------
extern __shared__ char dsm[];
__global__ void __launch_bounds__(256, 2) gemm_p_v4(float* __restrict__ out) {
    u32 sb = smem_u32(dsm);
    float* Cs = (float*)(dsm + NSTAGE * STAGE_P);     // [23][128]
    float* sU = Cs + TSTEPS * 128;                    // [184]

    int tid = threadIdx.x, wid = tid >> 5, lane = tid & 31;
    int wm = wid & 3, wn = wid >> 2;
    int rowBase = blockIdx.x * 128, colBase = blockIdx.y * 128;
    int b0 = rowBase / TSTEPS;

    for (int i = tid; i < TSTEPS * 128; i += 256)
        Cs[i] = g_C[(i >> 7) * HIDDEN + colBase + (i & 127)];
    {
        int cnt = BATCH * TSTEPS - b0 * TSTEPS;
        if (cnt > 184) cnt = 184;
        for (int i = tid; i < cnt; i += 256) sU[i] = g_U[b0 * TSTEPS + i];
    }

    float accH[2][8][4];
    #pragma unroll
    for (int a = 0; a < 2; a++)
        #pragma unroll
        for (int b = 0; b < 8; b++)
            #pragma unroll
            for (int c = 0; c < 4; c++) accH[a][b][c] = 0.f;

    const int NCH = INPUT_DIM / KCH;   // 8
    stage_load_p(sb, rowBase, colBase, 0, tid);
    cp_commit();
    stage_load_p(sb + STAGE_P, rowBase, colBase, KCH, tid);
    cp_commit();

    int buf = 0;
    for (int c = 0; c < NCH; c++) {
        cp_wait1();
        __syncthreads();
        if (c + 2 < NCH) {
            int nb = buf + 2; if (nb >= NSTAGE) nb -= NSTAGE;
            stage_load_p(sb + nb * STAGE_P, rowBase, colBase, (c + 2) * KCH, tid);
        }
        cp_commit();
        compute_p(sb + buf * STAGE_P, accH, wm, wn, lane);
        if (++buf == NSTAGE) buf = 0;
    }

    int quad = lane >> 2, tq = lane & 3;
    #pragma unroll
    for (int mt = 0; mt < 2; mt++) {
        #pragma unroll
        for (int h = 0; h < 2; h++) {
            int r = rowBase + wm * 32 + mt * 16 + quad + h * 8;
            int bb = r / TSTEPS;
            int tr = r - bb * TSTEPS;
            const float* u = sU + (bb - b0) * TSTEPS;
            #pragma unroll
            for (int nt = 0; nt < 8; nt++) {
                int cc = wn * 64 + nt * 8 + tq * 2;
                float v0 = accH[mt][nt][h * 2];
                float v1 = accH[mt][nt][h * 2 + 1];
                for (int s = 0; s <= tr; ++s) {
                    float us = u[s];
                    const float* cp = Cs + (tr - s) * 128 + cc;
                    v0 = fmaf(us, cp[0], v0);
                    v1 = fmaf(us, cp[1], v1);
                }
                size_t off = (size_t)r * HIDDEN + colBase + cc;
                if (tr == 0) {
                    float h0 = v0 >= 0.f ? v0 : SLOPE * v0;
                    float h1 = v1 >= 0.f ? v1 : SLOPE * v1;
                    *(float2*)(out + off) = make_float2(h0, h1);
                    *(u32*)(g_Hf0 + (size_t)bb * HIDDEN + colBase + cc) = pack_h2(h0, h1);
                } else {
                    *(float2*)(g_P + off) = make_float2(v0, v1);
                }
            }
        }
    }
}

// ---------------------------------------------------------------------------
// gemm_h: H_t = lrelu(P_t + H_{t-1} @ (WhH + WhL)^T).  grid (64, 4), 256 thr.
// hi term fp32-acc, lo term fp16-acc.
// ---------------------------------------------------------------------------
__global__ void __launch_bounds__(256, 2) gemm_h_v4(float* __restrict__ out, int t, int par) {
    u32 sb = smem_u32(dsm);
    int tid = threadIdx.x, wid = tid >> 5, lane = tid & 31;
    int wm = wid & 3, wn = wid >> 2;
    int rowBase = blockIdx.x * 128, colBase = blockIdx.y * 128;

    const u16* Af = par ? g_Hf1 : g_Hf0;
    u16* Df = par ? g_Hf0 : g_Hf1;

    float accH[2][8][4];
    u32 accL[2][8][2];
    #pragma unroll
    for (int a = 0; a < 2; a++)
        #pragma unroll
        for (int b = 0; b < 8; b++) {
            #pragma unroll
            for (int c = 0; c < 4; c++) accH[a][b][c] = 0.f;
            accL[a][b][0] = 0u; accL[a][b][1] = 0u;
        }

    const int NCH = HIDDEN / KCH;   // 16
    stage_load_h(sb, Af, rowBase, colBase, 0, tid);
    cp_commit();
    stage_load_h(sb + STAGE_H, Af, rowBase, colBase, KCH, tid);
    cp_commit();

    int buf = 0;
    for (int c = 0; c < NCH; c++) {
        cp_wait1();
        __syncthreads();
        if (c + 2 < NCH) {
            int nb = buf + 2; if (nb >= NSTAGE) nb -= NSTAGE;
            stage_load_h(sb + nb * STAGE_H, Af, rowBase, colBase, (c + 2) * KCH, tid);
        }
        cp_commit();
        compute_h(sb + buf * STAGE_H, accH, accL, wm, wn, lane);
        if (++buf == NSTAGE) buf = 0;
    }

    int quad = lane >> 2, tq = lane & 3;
    #pragma unroll
    for (int mt = 0; mt < 2; mt++) {
        #pragma unroll
        for (int h = 0; h < 2; h++) {
            int m = rowBase + wm * 32 + mt * 16 + quad + h * 8;
            size_t off0 = ((size_t)m * TSTEPS + t) * HIDDEN + colBase;
            size_t hoff0 = (size_t)m * HIDDEN + colBase;
            #pragma unroll
            for (int nt = 0; nt < 8; nt++) {
                int cc = wn * 64 + nt * 8 + tq * 2;
                float2 p = *(const float2*)(g_P + off0 + cc);
                __half2 lh = *reinterpret_cast<__half2*>(&accL[mt][nt][h]);
                float2 lo = __half22float2(lh);
                float v0 = accH[mt][nt][h * 2] + lo.x + p.x;
                float v1 = accH[mt][nt][h * 2 + 1] + lo.y + p.y;
                v0 = v0 >= 0.f ? v0 : SLOPE * v0;
                v1 = v1 >= 0.f ? v1 : SLOPE * v1;
                *(float2*)(out + off0 + cc) = make_float2(v0, v1);
                *(u32*)(Df + hoff0 + cc) = pack_h2(v0, v1);
            }
        }
    }
}

// ---------------------------------------------------------------------------
extern "C" void kernel_launch(void* const* d_in, const int* in_sizes, int n_in,
                              void* d_out, int out_size) {
    const float* X  = (const float*)d_in[0];
    const float* A  = (const float*)d_in[1];
    const float* Bv = (const float*)d_in[2];
    const float* Wh = (const float*)d_in[3];
    const float* Wm = (const float*)d_in[4];
    const float* Wx = (const float*)d_in[5];
    const float* ex = (const float*)d_in[6];
    float* out = (float*)d_out;

    cudaFuncSetAttribute(gemm_p_v4, cudaFuncAttributeMaxDynamicSharedMemorySize, SMEM_P);
    cudaFuncSetAttribute(gemm_h_v4, cudaFuncAttributeMaxDynamicSharedMemorySize, SMEM_H);

    // Order chosen so the ncu capture slot (-s 5 -c 1) lands on a GEMM kernel.
    convX_U<<<(BATCH * TSTEPS) / 8, 256>>>(X, ex);
    convert_Wh<<<1024, 256>>>(Wh);
    convert_Wx<<<512, 256>>>(Wx);
    compute_C<<<1, 512>>>(A, Bv, Wm);

    dim3 gp((BATCH * TSTEPS) / 128, HIDDEN / 128);
    gemm_p_v4<<<gp, 256, SMEM_P>>>(out);

    dim3 gh(BATCH / 128, HIDDEN / 128);
    for (int t = 1; t < TSTEPS; ++t)
        gemm_h_v4<<<gh, 256, SMEM_H>>>(out, t, (t - 1) & 1);
}